// round 16
// baseline (speedup 1.0000x reference)
#include <cuda_runtime.h>
#include <math.h>

#define B_  512
#define T_  128
#define V_  59
#define H_  512
#define H3_ 1536
#define BT_ (B_*T_)

// ---------------- scratch (static __device__, no allocations) ----------------
__device__ float g_gif[(size_t)BT_*H3_];   // forward  gi (includes bih)
__device__ float g_gib[(size_t)BT_*H3_];   // backward gi (includes bih)
__device__ float g_hf [(size_t)BT_*H_];    // forward  pre-update hiddens
__device__ float g_hb [(size_t)BT_*H_];    // backward pre-update hiddens (time-aligned)
__device__ float g_num[T_];
__device__ float g_den[T_];

// ---------------- f32x2 helpers (Blackwell packed fp32) ----------------
typedef unsigned long long ull;
__device__ __forceinline__ ull pk2(float a, float b) {
    ull r; asm("mov.b64 %0, {%1, %2};" : "=l"(r) : "f"(a), "f"(b)); return r;
}
__device__ __forceinline__ void upk2(ull v, float& a, float& b) {
    asm("mov.b64 {%0, %1}, %2;" : "=f"(a), "=f"(b) : "l"(v));
}
__device__ __forceinline__ void fma2(ull& d, ull a, ull b) {
    asm("fma.rn.f32x2 %0, %1, %2, %3;" : "=l"(d) : "l"(a), "l"(b), "l"(d));
}

// ---------------- init ----------------
__global__ void k_init() {
    int idx = blockIdx.x * 256 + threadIdx.x;
    if (idx < B_*H_) {
        int b = idx >> 9, j = idx & 511;
        g_hf[(size_t)b*T_*H_ + j] = 0.f;
        g_hb[(size_t)b*T_*H_ + (size_t)(T_-1)*H_ + j] = 0.f;
    }
    if (idx < T_) { g_num[idx] = 0.f; g_den[idx] = 0.f; }
}

// ---------------- phase 1: fused gi GEMM, FFMA2 ----------------
// tile 64 bt x 64 c, 256 threads. accA shares [values;masks] K=118 part;
// accF/accB add delta parts against shared Wd columns.
__global__ __launch_bounds__(256) void k_phase1(
    const float* __restrict__ values, const float* __restrict__ masks,
    const float* __restrict__ df,     const float* __restrict__ db,
    const float* __restrict__ Wih,    const float* __restrict__ bih)
{
    __shared__ float sx [64*36];   // x tile, row-major [row][36]
    __shared__ float sx2[64*36];   // second x tile (backward deltas)
    __shared__ float sw [32*66];   // w tile transposed [kk][66]

    int tid = threadIdx.x;
    int tx = tid & 15, ty = tid >> 4;
    int rBase = blockIdx.y * 64;   // bt rows
    int cBase = blockIdx.x * 64;   // output cols

    ull accA[4][2], accF[4][2], accB[4][2];
    #pragma unroll
    for (int i = 0; i < 4; i++)
        #pragma unroll
        for (int jp = 0; jp < 2; jp++) { accA[i][jp]=0ull; accF[i][jp]=0ull; accB[i][jp]=0ull; }

    // ---- part A: k in [0,118) (values|masks), padded to 128 ----
    for (int k0 = 0; k0 < 128; k0 += 32) {
        for (int l = tid; l < 64*32; l += 256) {
            int r = l >> 5, kk = l & 31;
            int k = k0 + kk;
            int bt = rBase + r;
            float xv = 0.f;
            if (k < 59)       xv = values[(size_t)bt*V_ + k];
            else if (k < 118) xv = masks [(size_t)bt*V_ + (k - 59)];
            sx[r*36 + kk] = xv;
        }
        for (int l = tid; l < 64*32; l += 256) {
            int c = l >> 5, kk = l & 31;
            int k = k0 + kk;
            sw[kk*66 + c] = (k < 118) ? Wih[(size_t)(cBase + c)*177 + k] : 0.f;
        }
        __syncthreads();
        #pragma unroll
        for (int k4 = 0; k4 < 8; k4++) {
            float4 x4[4];
            #pragma unroll
            for (int i = 0; i < 4; i++)
                x4[i] = *reinterpret_cast<const float4*>(&sx[(ty + 16*i)*36 + k4*4]);
            #pragma unroll
            for (int c = 0; c < 4; c++) {
                int kk = k4*4 + c;
                ull w0 = *reinterpret_cast<const ull*>(&sw[kk*66 + 2*tx]);
                ull w1 = *reinterpret_cast<const ull*>(&sw[kk*66 + 32 + 2*tx]);
                #pragma unroll
                for (int i = 0; i < 4; i++) {
                    float hv = (c==0)?x4[i].x:(c==1)?x4[i].y:(c==2)?x4[i].z:x4[i].w;
                    ull h2 = pk2(hv, hv);
                    fma2(accA[i][0], h2, w0);
                    fma2(accA[i][1], h2, w1);
                }
            }
        }
        __syncthreads();
    }

    // ---- part F/B: k in [0,59) against Wd = Wih[:,118:177], padded to 64 ----
    for (int k0 = 0; k0 < 64; k0 += 32) {
        for (int l = tid; l < 64*32; l += 256) {
            int r = l >> 5, kk = l & 31;
            int k = k0 + kk;
            int bt = rBase + r;
            int b = bt >> 7, t = bt & 127;
            int btf = (b << 7) + (127 - t);
            float fv = 0.f, bv = 0.f;
            if (k < 59) {
                fv = df[(size_t)bt *V_ + k];
                bv = db[(size_t)btf*V_ + k];
            }
            sx [r*36 + kk] = fv;
            sx2[r*36 + kk] = bv;
        }
        for (int l = tid; l < 64*32; l += 256) {
            int c = l >> 5, kk = l & 31;
            int k = k0 + kk;
            sw[kk*66 + c] = (k < 59) ? Wih[(size_t)(cBase + c)*177 + 118 + k] : 0.f;
        }
        __syncthreads();
        #pragma unroll
        for (int k4 = 0; k4 < 8; k4++) {
            float4 f4[4], b4[4];
            #pragma unroll
            for (int i = 0; i < 4; i++) {
                f4[i] = *reinterpret_cast<const float4*>(&sx [(ty + 16*i)*36 + k4*4]);
                b4[i] = *reinterpret_cast<const float4*>(&sx2[(ty + 16*i)*36 + k4*4]);
            }
            #pragma unroll
            for (int c = 0; c < 4; c++) {
                int kk = k4*4 + c;
                ull w0 = *reinterpret_cast<const ull*>(&sw[kk*66 + 2*tx]);
                ull w1 = *reinterpret_cast<const ull*>(&sw[kk*66 + 32 + 2*tx]);
                #pragma unroll
                for (int i = 0; i < 4; i++) {
                    float fv = (c==0)?f4[i].x:(c==1)?f4[i].y:(c==2)?f4[i].z:f4[i].w;
                    float bv = (c==0)?b4[i].x:(c==1)?b4[i].y:(c==2)?b4[i].z:b4[i].w;
                    ull fp = pk2(fv, fv), bp = pk2(bv, bv);
                    fma2(accF[i][0], fp, w0);
                    fma2(accF[i][1], fp, w1);
                    fma2(accB[i][0], bp, w0);
                    fma2(accB[i][1], bp, w1);
                }
            }
        }
        __syncthreads();
    }

    // ---- write: gif[bt,c] and gib[b, T-1-t, c] ----
    #pragma unroll
    for (int i = 0; i < 4; i++) {
        int bt = rBase + ty + 16*i;
        int b = bt >> 7, t = bt & 127;
        int btf = (b << 7) + (127 - t);
        #pragma unroll
        for (int jp = 0; jp < 2; jp++) {
            int c = cBase + jp*32 + 2*tx;
            float2 bias = *reinterpret_cast<const float2*>(&bih[c]);
            float a0, a1, f0, f1, b0v, b1v;
            upk2(accA[i][jp], a0, a1);
            upk2(accF[i][jp], f0, f1);
            upk2(accB[i][jp], b0v, b1v);
            float2 of = make_float2(a0 + f0 + bias.x, a1 + f1 + bias.y);
            float2 ob = make_float2(a0 + b0v + bias.x, a1 + b1v + bias.y);
            *reinterpret_cast<float2*>(&g_gif[(size_t)bt *H3_ + c]) = of;
            *reinterpret_cast<float2*>(&g_gib[(size_t)btf*H3_ + c]) = ob;
        }
    }
}

// ---------------- phase 2: one recurrence step, both directions ----------------
// grid (8 jblk, 8 bblk, 2 dir). CTA: 512 threads, tile 64 b x 64 j x 3 gates.
// Warp grid 4 col-blocks x 4 row-blocks; lanes = 8 col-pairs x 4 row-slots.
// w reads become 64B-broadcast LDS.64 (1 wavefront), h reads LDS.128 per k4.
#define SP_H   36
#define SP_W   66
#define HBF    (64*SP_H)                 // 2304
#define WBF    (32*SP_W)                 // 2112
#define BUF_F  (HBF + 3*WBF)             // 8640 floats per buffer
#define STEP_SMEM (2*BUF_F*(int)sizeof(float))

__global__ __launch_bounds__(512) void k_gru_step(
    const float* __restrict__ Whh, const float* __restrict__ bhh, int s)
{
    extern __shared__ float smem[];

    int dir = blockIdx.z;
    const float* gi = dir ? g_gib : g_gif;
    float* hbuf     = dir ? g_hb  : g_hf;
    int t_in  = dir ? (127 - s) : s;
    int t_out = dir ? (126 - s) : (s + 1);

    int tid = threadIdx.x;
    int wid  = tid >> 5, lane = tid & 31;
    int colb = wid & 3,  rowb = wid >> 2;       // 4 x 4 warp grid
    int cp   = lane & 7, rq   = lane >> 3;      // 8 col-pairs x 4 row-slots
    int jloc  = colb*16 + 2*cp;                 // local col (pair start)
    int rbase = rowb*16 + rq;                   // rows rbase + 4*i
    int bBase = blockIdx.y * 64;
    int jBase = blockIdx.x * 64;

    ull acc[3][4];
    #pragma unroll
    for (int g = 0; g < 3; g++)
        #pragma unroll
        for (int i = 0; i < 4; i++) acc[g][i] = 0ull;

    // cooperative-load indices: one float4 of h, three float4 of w per thread
    int lr = tid >> 3, lq = tid & 7;
    const float* hsrc = &hbuf[((size_t)(bBase + lr)*T_ + t_in)*H_ + lq*4];

    // ---- prologue: tile 0 -> buffer 0 ----
    {
        float4 ph = *reinterpret_cast<const float4*>(hsrc);
        float4 pw[3];
        #pragma unroll
        for (int g = 0; g < 3; g++)
            pw[g] = *reinterpret_cast<const float4*>(
                &Whh[(size_t)(g*H_ + jBase + lr)*H_ + lq*4]);

        *reinterpret_cast<float4*>(&smem[lr*SP_H + lq*4]) = ph;
        #pragma unroll
        for (int g = 0; g < 3; g++) {
            float* bw = smem + HBF + g*WBF;
            bw[(lq*4+0)*SP_W + lr] = pw[g].x;
            bw[(lq*4+1)*SP_W + lr] = pw[g].y;
            bw[(lq*4+2)*SP_W + lr] = pw[g].z;
            bw[(lq*4+3)*SP_W + lr] = pw[g].w;
        }
    }
    __syncthreads();

    // ---- mainloop over 16 k-tiles ----
    for (int kt = 0; kt < 16; kt++) {
        int cur = kt & 1;
        float* buf = smem + cur*BUF_F;

        float4 ph, pw[3];
        if (kt < 15) {
            int k0 = (kt + 1) * 32;
            ph = *reinterpret_cast<const float4*>(hsrc + k0);
            #pragma unroll
            for (int g = 0; g < 3; g++)
                pw[g] = *reinterpret_cast<const float4*>(
                    &Whh[(size_t)(g*H_ + jBase + lr)*H_ + k0 + lq*4]);
        }

        const float* bh  = buf;
        const float* bw0 = buf + HBF;
        const float* bw1 = buf + HBF + WBF;
        const float* bw2 = buf + HBF + 2*WBF;
        #pragma unroll
        for (int k4 = 0; k4 < 8; k4++) {
            float4 h4[4];
            #pragma unroll
            for (int i = 0; i < 4; i++)
                h4[i] = *reinterpret_cast<const float4*>(
                    &bh[(rbase + 4*i)*SP_H + k4*4]);
            #pragma unroll
            for (int c = 0; c < 4; c++) {
                int kk = k4*4 + c;
                ull w0 = *reinterpret_cast<const ull*>(&bw0[kk*SP_W + jloc]);
                ull w1 = *reinterpret_cast<const ull*>(&bw1[kk*SP_W + jloc]);
                ull w2 = *reinterpret_cast<const ull*>(&bw2[kk*SP_W + jloc]);
                #pragma unroll
                for (int i = 0; i < 4; i++) {
                    float hv = (c == 0) ? h4[i].x : (c == 1) ? h4[i].y
                             : (c == 2) ? h4[i].z : h4[i].w;
                    ull h2 = pk2(hv, hv);
                    fma2(acc[0][i], h2, w0);
                    fma2(acc[1][i], h2, w1);
                    fma2(acc[2][i], h2, w2);
                }
            }
        }

        if (kt < 15) {
            float* nbuf = smem + (1 - cur)*BUF_F;
            *reinterpret_cast<float4*>(&nbuf[lr*SP_H + lq*4]) = ph;
            #pragma unroll
            for (int g = 0; g < 3; g++) {
                float* bwn = nbuf + HBF + g*WBF;
                bwn[(lq*4+0)*SP_W + lr] = pw[g].x;
                bwn[(lq*4+1)*SP_W + lr] = pw[g].y;
                bwn[(lq*4+2)*SP_W + lr] = pw[g].z;
                bwn[(lq*4+3)*SP_W + lr] = pw[g].w;
            }
        }
        __syncthreads();
    }

    // ---- gate epilogue: 4 rows x 2 cols per thread ----
    int jj = jBase + jloc;
    float2 bhr = *reinterpret_cast<const float2*>(&bhh[jj]);
    float2 bhz = *reinterpret_cast<const float2*>(&bhh[H_  + jj]);
    float2 bhn = *reinterpret_cast<const float2*>(&bhh[2*H_ + jj]);
    #pragma unroll
    for (int i = 0; i < 4; i++) {
        int b = bBase + rbase + 4*i;
        const float* girow = &gi[((size_t)b*T_ + s)*H3_];
        float2 gir = *reinterpret_cast<const float2*>(&girow[jj]);
        float2 giz = *reinterpret_cast<const float2*>(&girow[H_  + jj]);
        float2 gin = *reinterpret_cast<const float2*>(&girow[2*H_ + jj]);
        float2 hp  = *reinterpret_cast<const float2*>(
            &hbuf[((size_t)b*T_ + t_in)*H_ + jj]);

        float ar[2], az[2], an[2];
        upk2(acc[0][i], ar[0], ar[1]);
        upk2(acc[1][i], az[0], az[1]);
        upk2(acc[2][i], an[0], an[1]);

        float2 ho;
        {
            float r = 1.f / (1.f + __expf(-(gir.x + ar[0] + bhr.x)));
            float z = 1.f / (1.f + __expf(-(giz.x + az[0] + bhz.x)));
            float n = tanhf(gin.x + r*(an[0] + bhn.x));
            ho.x = (1.f - z)*n + z*hp.x;
        }
        {
            float r = 1.f / (1.f + __expf(-(gir.y + ar[1] + bhr.y)));
            float z = 1.f / (1.f + __expf(-(giz.y + az[1] + bhz.y)));
            float n = tanhf(gin.y + r*(an[1] + bhn.y));
            ho.y = (1.f - z)*n + z*hp.y;
        }
        *reinterpret_cast<float2*>(&hbuf[((size_t)b*T_ + t_out)*H_ + jj]) = ho;
    }
}

// ---------------- phase 3: fused regression chain + loss ----------------
#define P3_WBIG  0                       // [59][237]  Wf|Wc|Wi rows
#define P3_W     (P3_WBIG + 59*237)      // [59][33]   Wh k-tile
#define P3_H     (P3_W    + 59*33)       // [16][33]   h2 k-tile
#define P3_XV    (P3_H    + 16*33)       // [16][60]
#define P3_VAL   (P3_XV   + 16*60)
#define P3_MSK   (P3_VAL  + 16*60)
#define P3_XH    (P3_MSK  + 16*60)
#define P3_RED   (P3_XH   + 16*60)       // [256]
#define P3_TOTAL (P3_RED  + 256)         // floats

__global__ __launch_bounds__(256) void k_post(
    const float* __restrict__ values, const float* __restrict__ masks,
    const float* __restrict__ Wh, const float* __restrict__ bh,
    const float* __restrict__ Wf, const float* __restrict__ bf,
    const float* __restrict__ Wc, const float* __restrict__ bc,
    const float* __restrict__ Wi, const float* __restrict__ bi,
    float* __restrict__ out)
{
    extern __shared__ float smem[];
    float* s_wbig = smem + P3_WBIG;
    float* s_w    = smem + P3_W;
    float* s_h    = smem + P3_H;
    float* s_xv   = smem + P3_XV;
    float* s_val  = smem + P3_VAL;
    float* s_msk  = smem + P3_MSK;
    float* s_xh   = smem + P3_XH;
    float* s_red  = smem + P3_RED;

    int t = blockIdx.x;
    int bBase = blockIdx.y * 16;
    int tid = threadIdx.x;
    int v   = tid & 63;
    int grp = tid >> 6;

    for (int l = tid; l < 59*236; l += 256) {
        int r = l / 236, c = l - r*236;
        float w;
        if (c < 59)       w = Wf[r*59 + c];
        else if (c < 177) w = Wc[r*118 + (c - 59)];
        else              w = Wi[r*59 + (c - 177)];
        s_wbig[r*237 + c] = w;
    }

    float acc[4] = {0.f, 0.f, 0.f, 0.f};
    for (int k0 = 0; k0 < 1024; k0 += 32) {
        for (int l = tid; l < 59*32; l += 256) {
            int r = l >> 5, kk = l & 31;
            s_w[r*33 + kk] = Wh[(size_t)r*1024 + k0 + kk];
        }
        for (int l = tid; l < 16*32; l += 256) {
            int r = l >> 5, kk = l & 31;
            int k = k0 + kk;
            int b = bBase + r;
            float hv = (k < 512)
                ? g_hf[((size_t)b*T_ + t)*H_ + k]
                : g_hb[((size_t)b*T_ + t)*H_ + (k - 512)];
            s_h[r*33 + kk] = hv;
        }
        __syncthreads();
        if (v < 59) {
            #pragma unroll
            for (int kk = 0; kk < 32; kk++) {
                float w = s_w[v*33 + kk];
                #pragma unroll
                for (int i = 0; i < 4; i++) acc[i] += w * s_h[(grp*4 + i)*33 + kk];
            }
        }
        __syncthreads();
    }
    if (v < 59) {
        float bias = bh[v];
        #pragma unroll
        for (int i = 0; i < 4; i++) s_xv[(grp*4 + i)*60 + v] = acc[i] + bias;
    }
    for (int l = tid; l < 16*59; l += 256) {
        int r = l / 59, kk = l - r*59;
        size_t g = ((size_t)(bBase + r)*T_ + t)*V_ + kk;
        s_val[r*60 + kk] = values[g];
        s_msk[r*60 + kk] = masks [g];
    }
    __syncthreads();

    if (v < 59) {
        float xh[4];
        float bias = bf[v] + bc[v];
        #pragma unroll
        for (int i = 0; i < 4; i++) xh[i] = bias;
        for (int k = 0; k < 59; k++) {
            float wf  = (k == v) ? 0.f : s_wbig[v*237 + k];
            float wc1 = s_wbig[v*237 + 59 + k];
            float wc2 = s_wbig[v*237 + 118 + k];
            #pragma unroll
            for (int i = 0; i < 4; i++) {
                int r = grp*4 + i;
                xh[i] += s_val[r*60 + k]*wf + s_xv[r*60 + k]*wc1 + s_msk[r*60 + k]*wc2;
            }
        }
        #pragma unroll
        for (int i = 0; i < 4; i++) s_xh[(grp*4 + i)*60 + v] = xh[i];
    }
    __syncthreads();

    float lnum = 0.f, lden = 0.f;
    if (v < 59) {
        #pragma unroll
        for (int i = 0; i < 4; i++) {
            int r = grp*4 + i;
            int b = bBase + r;
            float imp = bi[v];
            for (int k = 0; k < 59; k++) imp += s_xh[r*60 + k] * s_wbig[v*237 + 177 + k];
            float val = s_val[r*60 + v], m = s_msk[r*60 + v];
            out[((size_t)b*T_ + t)*V_ + v] = m*val + (1.f - m)*imp;
            lnum += fabsf(val - imp) * m;
            lden += m;
        }
    }
    s_red[tid] = lnum; __syncthreads();
    for (int st = 128; st > 0; st >>= 1) { if (tid < st) s_red[tid] += s_red[tid + st]; __syncthreads(); }
    if (tid == 0) atomicAdd(&g_num[t], s_red[0]);
    __syncthreads();
    s_red[tid] = lden; __syncthreads();
    for (int st = 128; st > 0; st >>= 1) { if (tid < st) s_red[tid] += s_red[tid + st]; __syncthreads(); }
    if (tid == 0) atomicAdd(&g_den[t], s_red[0]);
}

// ---------------- final loss reduction ----------------
__global__ void k_loss(float* __restrict__ out) {
    __shared__ float sr[128];
    int t = threadIdx.x;
    sr[t] = g_num[t] / (g_den[t] + 1e-5f);
    __syncthreads();
    for (int s = 64; s > 0; s >>= 1) { if (t < s) sr[t] += sr[t + s]; __syncthreads(); }
    if (t == 0) out[(size_t)B_*T_*V_] = sr[0];
}

// ---------------- launch ----------------
extern "C" void kernel_launch(void* const* d_in, const int* in_sizes, int n_in,
                              void* d_out, int out_size) {
    const float* values = (const float*)d_in[0];
    const float* masks  = (const float*)d_in[1];
    const float* df     = (const float*)d_in[2];
    const float* db     = (const float*)d_in[3];
    const float* Wih    = (const float*)d_in[4];
    const float* Whh    = (const float*)d_in[5];
    const float* bih    = (const float*)d_in[6];
    const float* bhh    = (const float*)d_in[7];
    const float* Wh     = (const float*)d_in[8];
    const float* bh     = (const float*)d_in[9];
    const float* Wf     = (const float*)d_in[10];
    const float* bf     = (const float*)d_in[11];
    const float* Wc     = (const float*)d_in[12];
    const float* bc     = (const float*)d_in[13];
    const float* Wi     = (const float*)d_in[14];
    const float* bi     = (const float*)d_in[15];
    float* out = (float*)d_out;

    cudaFuncSetAttribute(k_post, cudaFuncAttributeMaxDynamicSharedMemorySize,
                         P3_TOTAL * (int)sizeof(float));
    cudaFuncSetAttribute(k_gru_step, cudaFuncAttributeMaxDynamicSharedMemorySize,
                         STEP_SMEM);

    k_init<<<(B_*H_ + 255)/256, 256>>>();
    k_phase1<<<dim3(H3_/64, BT_/64), 256>>>(values, masks, df, db, Wih, bih);
    for (int s = 0; s < T_ - 1; s++)
        k_gru_step<<<dim3(8, 8, 2), 512, STEP_SMEM>>>(Whh, bhh, s);
    k_post<<<dim3(T_, B_/16), 256, P3_TOTAL * sizeof(float)>>>(
        values, masks, Wh, bh, Wf, bf, Wc, bc, Wi, bi, out);
    k_loss<<<1, 128>>>(out);
}